// round 13
// baseline (speedup 1.0000x reference)
#include <cuda_runtime.h>
#include <stdint.h>

#define BN      16384
#define IN_DIM  256
#define HID     128
#define NCLS    8
#define T_STEPS 64
#define BETA    0.9f
#define NSM     148

// Scratch (no cudaMalloc allowed)
__device__ float g_cur1[BN * HID];          // 8 MB
__device__ uint4 g_masks[T_STEPS * BN];     // 16 MB  [t][s] spike masks
__device__ float g_W1T[IN_DIM * HID];       // 128 KB W1 transposed: [k][h]

// packed fp32x2 FMA: per-32-bit-lane IEEE fma.rn.f32 — lanes independent.
static __device__ __forceinline__ void ffma2(unsigned long long& d,
                                             unsigned long long a,
                                             unsigned long long b)
{
    asm("fma.rn.f32x2 %0, %1, %2, %0;" : "+l"(d) : "l"(a), "l"(b));
}

static __device__ __forceinline__ unsigned long long fdup(float v)
{
    unsigned long long r;
    unsigned u = __float_as_uint(v);
    asm("mov.b64 %0, {%1, %1};" : "=l"(r) : "r"(u));
    return r;
}

// ---------------------------------------------------------------------------
// K0: W1T[k][h] = W1[h][k] — tiled transpose, coalesced both sides.
// ---------------------------------------------------------------------------
__global__ void k0_w1t(const float* __restrict__ W1)
{
    __shared__ float t[32][33];
    const int kb = blockIdx.x * 32;
    const int hb = blockIdx.y * 32;
    const int lx = threadIdx.x;
    const int ly = threadIdx.y;
#pragma unroll
    for (int i = 0; i < 4; i++)
        t[ly + i * 8][lx] = W1[(hb + ly + i * 8) * IN_DIM + kb + lx];
    __syncthreads();
#pragma unroll
    for (int i = 0; i < 4; i++)
        g_W1T[(kb + ly + i * 8) * HID + hb + lx] = t[lx][ly + i * 8];
}

// ---------------------------------------------------------------------------
// K1: cur1 = x @ W1^T + b1. (R12 FFMA2 math, bitwise identical) with
// DOUBLE-BUFFERED smem: one __syncthreads per chunk.
// CTA 64s x 128h, 128 threads, thread tile 8s x 8h (4 hid-pairs).
// Dynamic smem: xs[2][64*36] (18.4 KB) + ws[2][32*128] (32 KB) = 50 KB.
// ---------------------------------------------------------------------------
#define XS_STRIDE 36
#define XS_BYTES  (64 * XS_STRIDE * 4)      // 9216
#define WS_BYTES  (32 * HID * 4)            // 16384
#define K1_SMEM   (2 * (XS_BYTES + WS_BYTES))

__global__ __launch_bounds__(128) void k1_fc1(const float* __restrict__ x,
                                              const float* __restrict__ b1)
{
    extern __shared__ char dsm[];
    float* xsb[2] = {(float*)dsm, (float*)(dsm + XS_BYTES)};
    float* wsb[2] = {(float*)(dsm + 2 * XS_BYTES),
                     (float*)(dsm + 2 * XS_BYTES + WS_BYTES)};

    const int tid = threadIdx.x;
    const int bs  = blockIdx.x * 64;
    const int c   = tid & 7;
    const int r   = tid >> 3;

    int xfs[4], xfk[4];
#pragma unroll
    for (int i = 0; i < 4; i++) {
        int f = i * 128 + tid;
        xfs[i] = f >> 3;
        xfk[i] = (f & 7) * 4;
    }

    float4 px[4], pw[8];
#pragma unroll
    for (int i = 0; i < 4; i++)
        px[i] = *(const float4*)&x[(bs + xfs[i]) * IN_DIM + xfk[i]];
#pragma unroll
    for (int i = 0; i < 8; i++) {
        int f  = i * 128 + tid;
        int kk = f >> 5;
        int h4 = (f & 31) * 4;
        pw[i] = *(const float4*)&g_W1T[kk * HID + h4];
    }

    unsigned long long acc2[4][8];
#pragma unroll
    for (int p = 0; p < 4; p++)
#pragma unroll
        for (int j = 0; j < 8; j++) acc2[p][j] = 0ull;

    for (int ch = 0; ch < IN_DIM / 32; ch++) {
        float* xs = xsb[ch & 1];
        float* ws = wsb[ch & 1];
#pragma unroll
        for (int i = 0; i < 4; i++)
            *(float4*)&xs[xfs[i] * XS_STRIDE + xfk[i]] = px[i];
#pragma unroll
        for (int i = 0; i < 8; i++) {
            int f  = i * 128 + tid;
            int kk = f >> 5;
            int h4 = (f & 31) * 4;
            *(float4*)&ws[kk * HID + h4] = pw[i];
        }
        __syncthreads();    // single barrier per chunk (double buffer)

        if (ch + 1 < IN_DIM / 32) {
            int kc = (ch + 1) * 32;
#pragma unroll
            for (int i = 0; i < 4; i++)
                px[i] = *(const float4*)&x[(bs + xfs[i]) * IN_DIM + kc + xfk[i]];
#pragma unroll
            for (int i = 0; i < 8; i++) {
                int f  = i * 128 + tid;
                int kk = f >> 5;
                int h4 = (f & 31) * 4;
                pw[i] = *(const float4*)&g_W1T[(kc + kk) * HID + h4];
            }
        }

#pragma unroll
        for (int k = 0; k < 32; k += 4) {
            float4 xv[8];
#pragma unroll
            for (int j = 0; j < 8; j++)
                xv[j] = *(const float4*)&xs[(c + 8 * j) * XS_STRIDE + k];
            ulonglong2 wa[4], wb[4];
#pragma unroll
            for (int kk = 0; kk < 4; kk++) {
                wa[kk] = *(const ulonglong2*)&ws[(k + kk) * HID + r * 8];
                wb[kk] = *(const ulonglong2*)&ws[(k + kk) * HID + r * 8 + 4];
            }
#pragma unroll
            for (int kk = 0; kk < 4; kk++) {
#pragma unroll
                for (int j = 0; j < 8; j++) {
                    float xf = (kk == 0) ? xv[j].x : (kk == 1) ? xv[j].y
                             : (kk == 2) ? xv[j].z : xv[j].w;
                    unsigned long long xx = fdup(xf);
                    ffma2(acc2[0][j], xx, wa[kk].x);
                    ffma2(acc2[1][j], xx, wa[kk].y);
                    ffma2(acc2[2][j], xx, wb[kk].x);
                    ffma2(acc2[3][j], xx, wb[kk].y);
                }
            }
        }
        // no trailing sync: next chunk writes the other buffer
    }

    float4 b1v0 = *(const float4*)&b1[r * 8];
    float4 b1v1 = *(const float4*)&b1[r * 8 + 4];
#pragma unroll
    for (int j = 0; j < 8; j++) {
        int s = bs + c + 8 * j;
        float4 o0, o1;
        o0.x = __uint_as_float((unsigned)(acc2[0][j] & 0xffffffffull)) + b1v0.x;
        o0.y = __uint_as_float((unsigned)(acc2[0][j] >> 32))           + b1v0.y;
        o0.z = __uint_as_float((unsigned)(acc2[1][j] & 0xffffffffull)) + b1v0.z;
        o0.w = __uint_as_float((unsigned)(acc2[1][j] >> 32))           + b1v0.w;
        o1.x = __uint_as_float((unsigned)(acc2[2][j] & 0xffffffffull)) + b1v1.x;
        o1.y = __uint_as_float((unsigned)(acc2[2][j] >> 32))           + b1v1.y;
        o1.z = __uint_as_float((unsigned)(acc2[3][j] & 0xffffffffull)) + b1v1.z;
        o1.w = __uint_as_float((unsigned)(acc2[3][j] >> 32))           + b1v1.w;
        *(float4*)&g_cur1[s * HID + r * 8]     = o0;
        *(float4*)&g_cur1[s * HID + r * 8 + 4] = o1;
    }
}

// ---------------------------------------------------------------------------
// K2: layer-1 LIF recurrence + spike mask packing (ballot). (== R9)
// ---------------------------------------------------------------------------
__global__ __launch_bounds__(256) void k2_lif1()
{
    __shared__ uint32_t sm[T_STEPS][8][4];

    const int tid  = threadIdx.x;
    const int w    = tid >> 5;
    const int lane = tid & 31;
    const int g    = w & 3;
    const int q    = w >> 2;
    const int sb   = blockIdx.x * 8 + q * 4;
    const int h    = g * 32 + lane;

    float cur[4], mem[4];
#pragma unroll
    for (int j = 0; j < 4; j++) {
        cur[j] = g_cur1[(sb + j) * HID + h];
        mem[j] = 0.0f;
    }

    for (int t = 0; t < T_STEPS; t++) {
#pragma unroll
        for (int j = 0; j < 4; j++) {
            float m  = mem[j];
            float rf = (m > 1.0f) ? 1.0f : 0.0f;
            m = fmaf(BETA, m, cur[j]) - rf;
            mem[j] = m;
            unsigned bal = __ballot_sync(0xffffffffu, m > 1.0f);
            if (lane == 0) sm[t][q * 4 + j][g] = bal;
        }
    }
    __syncthreads();

    for (int idx = tid; idx < T_STEPS * 8; idx += 256) {
        int t  = idx >> 3;
        int sl = idx & 7;
        g_masks[t * BN + blockIdx.x * 8 + sl] = *(const uint4*)&sm[t][sl][0];
    }
}

// ---------------------------------------------------------------------------
// K3: fused layer-2 LUT + LIF (trees bitwise == R9) with DEPTH-2 pipeline:
// while LIF-ing step t, the lut_tree for t+2 is in flight; masks prefetched
// at distance 3. Grid 148x2, 64 KB LUT, 128 thr (110-111 samples per block).
// ---------------------------------------------------------------------------
static __device__ __forceinline__ float4 f4add(float4 a, float4 b)
{
    return make_float4(a.x + b.x, a.y + b.y, a.z + b.z, a.w + b.w);
}

static __device__ __forceinline__ float4 lut_tree(const float* __restrict__ lut,
                                                  uint4 m, float4 b2v)
{
    uint32_t w[4] = {m.x, m.y, m.z, m.w};
    float4 sg[4];
#pragma unroll
    for (int g = 0; g < 4; g++) {
        const float* lg = &lut[g * 4096];
        uint32_t wg = w[g];
        float4 q0 = *(const float4*)&lg[            ((wg        & 255u) << 2)];
        float4 q1 = *(const float4*)&lg[1 * 1024 + (((wg >> 8)  & 255u) << 2)];
        float4 q2 = *(const float4*)&lg[2 * 1024 + (((wg >> 16) & 255u) << 2)];
        float4 q3 = *(const float4*)&lg[3 * 1024 + ((wg >> 24)          << 2)];
        sg[g] = f4add(f4add(q0, q1), f4add(q2, q3));
    }
    return f4add(f4add(f4add(sg[0], sg[1]), f4add(sg[2], sg[3])), b2v);
}

__global__ __launch_bounds__(128) void k3_lif2(const float* __restrict__ W2,
                                               const float* __restrict__ b2,
                                               float* __restrict__ out)
{
    extern __shared__ float lut[];   // [16][256] float4
    const int tid  = threadIdx.x;
    const int half = blockIdx.x & 1;
    const int bi   = blockIdx.x >> 1;          // 0..147

    {
        const int chunk = tid >> 3;            // 0..15
        const int bbase = (tid & 7) * 32;
        float w[4][8];
#pragma unroll
        for (int cc = 0; cc < 4; cc++)
#pragma unroll
            for (int j = 0; j < 8; j++)
                w[cc][j] = W2[(half * 4 + cc) * HID + chunk * 8 + j];

        for (int i = 0; i < 32; i++) {
            int byt = bbase + i;
            float4 v = make_float4(0.f, 0.f, 0.f, 0.f);
#pragma unroll
            for (int j = 0; j < 8; j++) {
                if ((byt >> j) & 1) {
                    v.x += w[0][j]; v.y += w[1][j];
                    v.z += w[2][j]; v.w += w[3][j];
                }
            }
            *(float4*)&lut[(chunk * 256 + byt) * 4] = v;
        }
    }
    __syncthreads();

    const int s_begin = (bi * BN) / NSM;
    const int s_end   = ((bi + 1) * BN) / NSM;
    const int s       = s_begin + tid;
    if (s >= s_end) return;

    float4 b2v = make_float4(b2[half * 4 + 0], b2[half * 4 + 1],
                             b2[half * 4 + 2], b2[half * 4 + 3]);

    const uint4* mp = &g_masks[s];

    uint4 mc = mp[2 * BN];                    // mask t = 2
    float4 cur = lut_tree(lut, mp[0],  b2v);  // current t = 0
    float4 nxt = lut_tree(lut, mp[BN], b2v);  // current t = 1

    float4 mem = make_float4(0.f, 0.f, 0.f, 0.f);
    float4 acc = mem, rst = mem;

#pragma unroll 2
    for (int t = 0; t < T_STEPS - 2; t++) {
        // prefetch mask t+3 (clamped)
        int tp = (t + 3 < T_STEPS) ? (t + 3) : (T_STEPS - 1);
        uint4 mnew = mp[(size_t)tp * BN];

        // tree for t+2 — two iterations of slack over the LDS chain
        float4 n2 = lut_tree(lut, mc, b2v);
        mc = mnew;

        // LIF step t
        mem.x = fmaf(BETA, mem.x, cur.x) - rst.x;
        mem.y = fmaf(BETA, mem.y, cur.y) - rst.y;
        mem.z = fmaf(BETA, mem.z, cur.z) - rst.z;
        mem.w = fmaf(BETA, mem.w, cur.w) - rst.w;
        rst.x = (mem.x > 1.0f) ? 1.0f : 0.0f;
        rst.y = (mem.y > 1.0f) ? 1.0f : 0.0f;
        rst.z = (mem.z > 1.0f) ? 1.0f : 0.0f;
        rst.w = (mem.w > 1.0f) ? 1.0f : 0.0f;
        acc.x += rst.x; acc.y += rst.y; acc.z += rst.z; acc.w += rst.w;

        cur = nxt;
        nxt = n2;
    }

    // t = 62
    mem.x = fmaf(BETA, mem.x, cur.x) - rst.x;
    mem.y = fmaf(BETA, mem.y, cur.y) - rst.y;
    mem.z = fmaf(BETA, mem.z, cur.z) - rst.z;
    mem.w = fmaf(BETA, mem.w, cur.w) - rst.w;
    rst.x = (mem.x > 1.0f) ? 1.0f : 0.0f;
    rst.y = (mem.y > 1.0f) ? 1.0f : 0.0f;
    rst.z = (mem.z > 1.0f) ? 1.0f : 0.0f;
    rst.w = (mem.w > 1.0f) ? 1.0f : 0.0f;
    acc.x += rst.x; acc.y += rst.y; acc.z += rst.z; acc.w += rst.w;
    cur = nxt;

    // t = 63
    mem.x = fmaf(BETA, mem.x, cur.x) - rst.x;
    mem.y = fmaf(BETA, mem.y, cur.y) - rst.y;
    mem.z = fmaf(BETA, mem.z, cur.z) - rst.z;
    mem.w = fmaf(BETA, mem.w, cur.w) - rst.w;
    acc.x += (mem.x > 1.0f) ? 1.0f : 0.0f;
    acc.y += (mem.y > 1.0f) ? 1.0f : 0.0f;
    acc.z += (mem.z > 1.0f) ? 1.0f : 0.0f;
    acc.w += (mem.w > 1.0f) ? 1.0f : 0.0f;

    *(float4*)&out[s * 8 + half * 4] = acc;
}

// ---------------------------------------------------------------------------
extern "C" void kernel_launch(void* const* d_in, const int* in_sizes, int n_in,
                              void* d_out, int out_size)
{
    const float* x  = (const float*)d_in[0];
    const float* W1 = (const float*)d_in[1];
    const float* b1 = (const float*)d_in[2];
    const float* W2 = (const float*)d_in[3];
    const float* b2 = (const float*)d_in[4];
    float* out = (float*)d_out;

    k0_w1t<<<dim3(8, 4), dim3(32, 8)>>>(W1);

    cudaFuncSetAttribute(k1_fc1, cudaFuncAttributeMaxDynamicSharedMemorySize, K1_SMEM);
    k1_fc1<<<BN / 64, 128, K1_SMEM>>>(x, b1);

    k2_lif1<<<BN / 8, 256>>>();

    cudaFuncSetAttribute(k3_lif2, cudaFuncAttributeMaxDynamicSharedMemorySize, 65536);
    k3_lif2<<<NSM * 2, 128, 65536>>>(W2, b2, out);
}